// round 1
// baseline (speedup 1.0000x reference)
#include <cuda_runtime.h>
#include <math.h>

#define Bc 2
#define Hc 1080
#define Wc 1920
#define Kc 2048
#define Pc 256
#define PATCH 64
#define PITCH 65   // 64 + 1 pad => conflict-free row & column scans

__global__ __launch_bounds__(256, 8)
void brief_desc_kernel(const float* __restrict__ img,
                       const float* __restrict__ kp,
                       const float* __restrict__ ori,
                       const float* __restrict__ oy1v,
                       const float* __restrict__ ox1v,
                       const float* __restrict__ oy2v,
                       const float* __restrict__ ox2v,
                       const float* __restrict__ thr,
                       const int*   __restrict__ radii,
                       float* __restrict__ out)
{
    __shared__ float S[PATCH * PITCH];
    __shared__ float red[8];

    const int blk = blockIdx.x;          // b*K + k
    const int b   = blk / Kc;
    const int tid = threadIdx.x;

    // --- keypoint, validity, orientation (redundant per-thread: broadcast loads) ---
    const float kpy = kp[blk * 2 + 0];
    const float kpx = kp[blk * 2 + 1];
    const float valid = (kpy >= 0.0f) ? 1.0f : 0.0f;
    const float y = fminf(fmaxf(kpy, 0.0f), (float)(Hc - 1));
    const float x = fminf(fmaxf(kpx, 0.0f), (float)(Wc - 1));
    const int iy = (int)rintf(y);        // rintf == round-half-to-even == jnp.round
    const int ix = (int)rintf(x);

    const float* imb = img + (size_t)b * Hc * Wc;
    const float theta = ori[(size_t)b * Hc * Wc + (size_t)iy * Wc + ix];
    float st, ct;
    sincosf(theta, &st, &ct);

    // patch origin: all sample centers land in [iy-24, iy+24]; box +-6 and the
    // SAT guard (-1) row/col need [iy-31, iy+30] -> 64 rows starting at iy-31.
    const int oy0 = iy - 31;
    const int ox0 = ix - 31;

    // --- cooperative patch load, zero-padded outside the image ---
    {
        const int col  = tid & 63;
        const int row0 = tid >> 6;       // 0..3
        #pragma unroll
        for (int i = 0; i < 16; i++) {
            const int r  = row0 + i * 4;
            const int gy = oy0 + r;
            const int gx = ox0 + col;
            float v = 0.0f;
            if (gy >= 0 && gy < Hc && gx >= 0 && gx < Wc)
                v = imb[(size_t)gy * Wc + gx];
            S[r * PITCH + col] = v;
        }
    }
    __syncthreads();

    // --- local inclusive SAT: row prefix then column prefix ---
    if (tid < 64) {
        float s = 0.0f;
        const int base = tid * PITCH;
        #pragma unroll
        for (int j = 0; j < 64; j++) { s += S[base + j]; S[base + j] = s; }
    }
    __syncthreads();
    if (tid < 64) {
        float s = 0.0f;
        #pragma unroll
        for (int i = 0; i < 64; i++) { s += S[i * PITCH + tid]; S[i * PITCH + tid] = s; }
    }
    __syncthreads();

    // --- per-pattern-point sampling ---
    const int   p    = tid;
    const float o_y1 = oy1v[p];
    const float o_x1 = ox1v[p];
    const float o_y2 = oy2v[p];
    const float o_x2 = ox2v[p];
    const int   r    = radii[p];
    const float dn   = (float)(2 * r + 1);
    const float invden = 1.0f / (dn * dn);

    const float p1y = y + (o_x1 * st + o_y1 * ct);
    const float p1x = x + (o_x1 * ct - o_y1 * st);
    const float p2y = y + (o_x2 * st + o_y2 * ct);
    const float p2x = x + (o_x2 * ct - o_y2 * st);

    auto boxavg = [&](float py, float px) -> float {
        // reference: round first, then clip
        const float jyf = fminf(fmaxf(rintf(py), 0.0f), (float)(Hc - 1));
        const float jxf = fminf(fmaxf(rintf(px), 0.0f), (float)(Wc - 1));
        const int ly = (int)jyf - oy0;   // in [7,55] by construction
        const int lx = (int)jxf - ox0;
        const int y1 = ly - r - 1, y2 = ly + r;   // y1 >= 0 guaranteed
        const int x1 = lx - r - 1, x2 = lx + r;
        const float s = S[y2 * PITCH + x2] - S[y1 * PITCH + x2]
                      - S[y2 * PITCH + x1] + S[y1 * PITCH + x1];
        return s * invden;
    };

    const float d = boxavg(p1y, p1x) - boxavg(p2y, p2x) - thr[p];

    // --- block reduction of sum(d^2) for the L2 norm ---
    float sq = d * d;
    #pragma unroll
    for (int off = 16; off; off >>= 1)
        sq += __shfl_xor_sync(0xffffffffu, sq, off);
    if ((tid & 31) == 0) red[tid >> 5] = sq;
    __syncthreads();
    const float tot = red[0] + red[1] + red[2] + red[3]
                    + red[4] + red[5] + red[6] + red[7];
    const float norm  = sqrtf(tot);
    const float scale = valid / fmaxf(norm, 1e-12f);

    out[(size_t)blk * Pc + p] = d * scale;
}

extern "C" void kernel_launch(void* const* d_in, const int* in_sizes, int n_in,
                              void* d_out, int out_size)
{
    const float* img  = (const float*)d_in[0];  // image (B,1,H,W)
    const float* kp   = (const float*)d_in[1];  // keypoints (B,K,2)
    const float* ori  = (const float*)d_in[2];  // orientation (B,1,H,W)
    const float* oy1  = (const float*)d_in[3];
    const float* ox1  = (const float*)d_in[4];
    const float* oy2  = (const float*)d_in[5];
    const float* ox2  = (const float*)d_in[6];
    const float* thr  = (const float*)d_in[7];
    const int*   rad  = (const int*)d_in[8];
    float* out = (float*)d_out;

    brief_desc_kernel<<<Bc * Kc, Pc>>>(img, kp, ori, oy1, ox1, oy2, ox2, thr, rad, out);
}